// round 16
// baseline (speedup 1.0000x reference)
#include <cuda_runtime.h>
#include <cuda_fp16.h>
#include <cstdint>

// Problem constants
#define BB   8
#define HH   64
#define WWD  64
#define DD   512
#define NHH  16
#define DKK  32
#define WSS  8
#define SHH  4
#define LL   4
#define MM   (BB*HH*WWD)          // 32768 tokens

// Scratch (device globals)
__device__ __half g_qkv16[(size_t)MM * 3 * DD];    // fused q|k|v, stride 1536
__device__ __half g_xn16[(size_t)MM * DD];
__device__ __half g_at16[(size_t)MM * DD];
__device__ __half g_h16 [(size_t)MM * 4 * DD];
__device__ __half g_wqkv16[(size_t)LL * DD * 3 * DD];
__device__ float  g_bqkv  [(size_t)LL * 3 * DD];
__device__ __half g_wo16 [(size_t)LL * DD * DD];
__device__ __half g_w1_16[(size_t)LL * DD * 4 * DD];
__device__ __half g_w2_16[(size_t)LL * 4 * DD * DD];
__device__ __half g_bias64[(size_t)LL * NHH * 64 * 64];

// ---------------------------------------------------------------------------
// Baseline-PTX helpers
// ---------------------------------------------------------------------------
__device__ __forceinline__ uint32_t smem_to_u32(const void* p) {
    uint32_t a;
    asm("{ .reg .u64 t; cvta.to.shared.u64 t, %1; cvt.u32.u64 %0, t; }" : "=r"(a) : "l"(p));
    return a;
}
__device__ __forceinline__ void cp_async16(uint32_t dst, const void* src) {
    asm volatile("cp.async.cg.shared.global [%0], [%1], 16;" :: "r"(dst), "l"(src));
}
#define CP_COMMIT() asm volatile("cp.async.commit_group;" ::: "memory")
template <int N> __device__ __forceinline__ void cp_wait_group() {
    asm volatile("cp.async.wait_group %0;" :: "n"(N) : "memory");
}
__device__ __forceinline__ void ldsm_x4(uint32_t* r, uint32_t addr) {
    asm volatile("ldmatrix.sync.aligned.m8n8.x4.shared.b16 {%0,%1,%2,%3}, [%4];"
        : "=r"(r[0]), "=r"(r[1]), "=r"(r[2]), "=r"(r[3]) : "r"(addr));
}
__device__ __forceinline__ void ldsm_x4_t(uint32_t* r, uint32_t addr) {
    asm volatile("ldmatrix.sync.aligned.m8n8.x4.trans.shared.b16 {%0,%1,%2,%3}, [%4];"
        : "=r"(r[0]), "=r"(r[1]), "=r"(r[2]), "=r"(r[3]) : "r"(addr));
}
__device__ __forceinline__ void mma_f16(float* c, const uint32_t* a, const uint32_t* b) {
    asm volatile(
        "mma.sync.aligned.m16n8k16.row.col.f32.f16.f16.f32 "
        "{%0,%1,%2,%3}, {%4,%5,%6,%7}, {%8,%9}, {%0,%1,%2,%3};\n"
        : "+f"(c[0]), "+f"(c[1]), "+f"(c[2]), "+f"(c[3])
        : "r"(a[0]), "r"(a[1]), "r"(a[2]), "r"(a[3]), "r"(b[0]), "r"(b[1]));
}

// ---------------------------------------------------------------------------
// fp16 tensor-core GEMM — occupancy experiment:
// 3 CTAs/SM (launch_bounds(128,3), reg budget 170), NO register frag dbuf.
// CTA 128x128, BK=64, 4 warps with 64x64 warp tiles, 2-stage smem dbuf.
// ---------------------------------------------------------------------------
#define HAS_STRIDE 72
#define HBS_STRIDE 136
#define HAS_BUF (128 * HAS_STRIDE)
#define HBS_BUF (64 * HBS_STRIDE)
#define SMEM_H  ((2 * HAS_BUF + 2 * HBS_BUF) * 2)   // 71680 bytes; x3 CTAs = 215K

__device__ __forceinline__ float gelu_f(float x) {
    float x3 = x * x * x;
    return 0.5f * x * (1.f + tanhf(0.7978845608028654f * (x + 0.044715f * x3)));
}
__device__ __forceinline__ void store2(float* C, size_t off, float v0, float v1) {
    float2 o; o.x = v0; o.y = v1;
    *reinterpret_cast<float2*>(C + off) = o;
}
__device__ __forceinline__ void store2(__half* C, size_t off, float v0, float v1) {
    *reinterpret_cast<__half2*>(C + off) = __floats2half2_rn(v0, v1);
}

template <int EPI, typename OutT>
__global__ void __launch_bounds__(128, 3) hgemm(
    const __half* __restrict__ A, const __half* __restrict__ Bm,
    const float* __restrict__ bias, const float* __restrict__ Rv,
    OutT* __restrict__ C, int M, int N, int K)
{
    extern __shared__ __half smh[];
    uint32_t sb = smem_to_u32(smh);
    const int tid = threadIdx.x;
    const int lane = tid & 31, wid = tid >> 5;
    const int wm = wid & 1, wn = wid >> 1;
    const int g = lane >> 2, tg = lane & 3;
    const int row0 = blockIdx.y * 128, col0 = blockIdx.x * 128;
    const int lrow = lane & 15, lcol8 = (lane >> 4) * 8;

    float acc[4][8][4];
#pragma unroll
    for (int i = 0; i < 4; i++)
#pragma unroll
        for (int j = 0; j < 8; j++)
#pragma unroll
            for (int k = 0; k < 4; k++) acc[i][j][k] = 0.f;

    const int NC = K >> 6;

    {
        uint32_t ad = sb, bd = sb + 2 * HAS_BUF * 2;
#pragma unroll
        for (int i = 0; i < 8; i++) {
            int ch = i * 128 + tid;
            int r = ch >> 3, c8 = ch & 7;
            cp_async16(ad + (r * HAS_STRIDE + c8 * 8) * 2,
                       A + (size_t)(row0 + r) * K + c8 * 8);
        }
#pragma unroll
        for (int i = 0; i < 8; i++) {
            int ch = i * 128 + tid;
            int r = ch >> 4, c8 = ch & 15;
            cp_async16(bd + (r * HBS_STRIDE + c8 * 8) * 2,
                       Bm + (size_t)r * N + col0 + c8 * 8);
        }
        CP_COMMIT();
    }

    for (int c = 0; c < NC; c++) {
        if (c + 1 < NC) {
            int kt = (c + 1) << 6;
            int nb = (c + 1) & 1;
            uint32_t ad = sb + (nb ? HAS_BUF * 2 : 0);
            uint32_t bd = sb + (2 * HAS_BUF + (nb ? HBS_BUF : 0)) * 2;
#pragma unroll
            for (int i = 0; i < 8; i++) {
                int ch = i * 128 + tid;
                int r = ch >> 3, c8 = ch & 7;
                cp_async16(ad + (r * HAS_STRIDE + c8 * 8) * 2,
                           A + (size_t)(row0 + r) * K + kt + c8 * 8);
            }
#pragma unroll
            for (int i = 0; i < 8; i++) {
                int ch = i * 128 + tid;
                int r = ch >> 4, c8 = ch & 15;
                cp_async16(bd + (r * HBS_STRIDE + c8 * 8) * 2,
                           Bm + (size_t)(kt + r) * N + col0 + c8 * 8);
            }
            CP_COMMIT();
            cp_wait_group<1>();
        } else {
            cp_wait_group<0>();
        }
        __syncthreads();

        uint32_t sbA = sb + ((c & 1) ? HAS_BUF * 2 : 0);
        uint32_t sbB = sb + (2 * HAS_BUF + ((c & 1) ? HBS_BUF : 0)) * 2;

#pragma unroll
        for (int j = 0; j < 4; j++) {
            const int kk = j * 16;
            uint32_t af[4][4], bf[8][2];
#pragma unroll
            for (int mt = 0; mt < 4; mt++) {
                int m = wm * 64 + mt * 16 + lrow;
                ldsm_x4(af[mt], sbA + (m * HAS_STRIDE + kk + lcol8) * 2);
            }
#pragma unroll
            for (int np = 0; np < 4; np++) {
                uint32_t r4[4];
                int n = wn * 64 + np * 16 + lcol8;
                ldsm_x4_t(r4, sbB + ((kk + lrow) * HBS_STRIDE + n) * 2);
                bf[2*np][0]   = r4[0]; bf[2*np][1]   = r4[1];
                bf[2*np+1][0] = r4[2]; bf[2*np+1][1] = r4[3];
            }
#pragma unroll
            for (int mt = 0; mt < 4; mt++)
#pragma unroll
                for (int nt = 0; nt < 8; nt++)
                    mma_f16(acc[mt][nt], af[mt], bf[nt]);
        }
        __syncthreads();
    }

#pragma unroll
    for (int mt = 0; mt < 4; mt++) {
#pragma unroll
        for (int nt = 0; nt < 8; nt++) {
            int r = row0 + wm * 64 + mt * 16 + g;
            int cc = col0 + wn * 64 + nt * 8 + tg * 2;
            float b0 = bias[cc], b1 = bias[cc + 1];
#pragma unroll
            for (int h = 0; h < 2; h++) {
                int rr = r + h * 8;
                size_t off = (size_t)rr * N + cc;
                float v0 = acc[mt][nt][h * 2 + 0] + b0;
                float v1 = acc[mt][nt][h * 2 + 1] + b1;
                if (EPI == 1) { v0 = gelu_f(v0); v1 = gelu_f(v1); }
                if (EPI == 2) {
                    float2 rv = *reinterpret_cast<const float2*>(Rv + off);
                    v0 += rv.x; v1 += rv.y;
                }
                store2(C, off, v0, v1);
            }
        }
    }
}

// ---------------------------------------------------------------------------
// ONE prep kernel: pack+convert Wqkv/bqkv, convert Wo/W1/W2, build bias64.
// ---------------------------------------------------------------------------
struct H8 { __half2 h[4]; };
#define U_WQKV (LL * DD * 3 * DD / 8)
#define U_WO   (LL * DD * DD / 8)
#define U_W1   (LL * DD * 4 * DD / 8)
#define U_W2   (LL * 4 * DD * DD / 8)
#define U_BIAS (LL * NHH * 64 * 64 / 8)
#define U_BQKV (LL * 3 * DD / 8)
#define U_TOTAL (U_WQKV + U_WO + U_W1 + U_W2 + U_BIAS + U_BQKV)

__device__ __forceinline__ void cvt8(const float* src, __half* dst) {
    const float4* p = reinterpret_cast<const float4*>(src);
    float4 a = p[0], b = p[1];
    H8 o;
    o.h[0] = __floats2half2_rn(a.x, a.y);
    o.h[1] = __floats2half2_rn(a.z, a.w);
    o.h[2] = __floats2half2_rn(b.x, b.y);
    o.h[3] = __floats2half2_rn(b.z, b.w);
    *reinterpret_cast<H8*>(dst) = o;
}

__global__ void prep_kernel(
    const float* __restrict__ Wq, const float* __restrict__ Wkv,
    const float* __restrict__ Wo, const float* __restrict__ W1,
    const float* __restrict__ W2, const float* __restrict__ rt,
    const float* __restrict__ bq, const float* __restrict__ bkv,
    __half* __restrict__ wqkv, __half* __restrict__ wo,
    __half* __restrict__ w1, __half* __restrict__ w2,
    __half* __restrict__ bias64, float* __restrict__ bqkv)
{
    int u = blockIdx.x * blockDim.x + threadIdx.x;
    if (u < U_WQKV) {
        size_t base = (size_t)u * 8;
        int j = (int)(base % 1536);
        int r = (int)((base / 1536) % DD);
        int l = (int)(base / (1536 * DD));
        const float* src = (j < DD)
            ? Wq  + ((size_t)l * DD + r) * DD + j
            : Wkv + ((size_t)l * DD + r) * 2 * DD + (j - DD);
        cvt8(src, wqkv + base);
        return;
    }
    u -= U_WQKV;
    if (u < U_WO) { cvt8(Wo + (size_t)u * 8, wo + (size_t)u * 8); return; }
    u -= U_WO;
    if (u < U_W1) { cvt8(W1 + (size_t)u * 8, w1 + (size_t)u * 8); return; }
    u -= U_W1;
    if (u < U_W2) { cvt8(W2 + (size_t)u * 8, w2 + (size_t)u * 8); return; }
    u -= U_W2;
    if (u < U_BIAS) {
        size_t base = (size_t)u * 8;
        int kk0 = (int)(base & 63);
        int qq  = (int)((base >> 6) & 63);
        int h   = (int)((base >> 12) & (NHH - 1));
        int l   = (int)(base >> 16);
        int rq = qq >> 3, cq = qq & 7;
        __half v[8];
#pragma unroll
        for (int e = 0; e < 8; e++) {
            int kk = kk0 + e;
            int rk = kk >> 3, ck = kk & 7;
            int ti = (rq - rk + 7) * 15 + (cq - ck + 7);
            v[e] = __float2half_rn(rt[((size_t)l * 225 + ti) * NHH + h]);
        }
        *reinterpret_cast<H8*>(bias64 + base) = *reinterpret_cast<H8*>(v);
        return;
    }
    u -= U_BIAS;
    if (u < U_BQKV) {
        size_t base = (size_t)u * 8;
        int j = (int)(base % 1536);
        int l = (int)(base / 1536);
        const float* src = (j < DD) ? bq + (size_t)l * DD + j
                                    : bkv + (size_t)l * 2 * DD + (j - DD);
        const float4* p = reinterpret_cast<const float4*>(src);
        float4 a = p[0], b = p[1];
        float4* d = reinterpret_cast<float4*>(bqkv + base);
        d[0] = a; d[1] = b;
    }
}

// ---------------------------------------------------------------------------
// LayerNorm: one warp per token, fp16 output
// ---------------------------------------------------------------------------
__global__ void ln_kernel(const float* __restrict__ x, const float* __restrict__ g,
                          const float* __restrict__ b, __half* __restrict__ out) {
    int warp = threadIdx.x >> 5, lane = threadIdx.x & 31;
    size_t row = (size_t)blockIdx.x * 8 + warp;
    const float4* xp = reinterpret_cast<const float4*>(x + row * DD);
    float4 v[4];
    float s = 0.f;
#pragma unroll
    for (int i = 0; i < 4; i++) {
        v[i] = xp[lane + i * 32];
        s += v[i].x + v[i].y + v[i].z + v[i].w;
    }
#pragma unroll
    for (int o = 16; o; o >>= 1) s += __shfl_xor_sync(0xFFFFFFFFu, s, o);
    float mean = s * (1.f / DD);
    float vs = 0.f;
#pragma unroll
    for (int i = 0; i < 4; i++) {
        float dx;
        dx = v[i].x - mean; vs += dx * dx;
        dx = v[i].y - mean; vs += dx * dx;
        dx = v[i].z - mean; vs += dx * dx;
        dx = v[i].w - mean; vs += dx * dx;
    }
#pragma unroll
    for (int o = 16; o; o >>= 1) vs += __shfl_xor_sync(0xFFFFFFFFu, vs, o);
    float rs = rsqrtf(vs * (1.f / DD) + 1e-5f);
    const float4* gp = reinterpret_cast<const float4*>(g);
    const float4* bp = reinterpret_cast<const float4*>(b);
#pragma unroll
    for (int i = 0; i < 4; i++) {
        int idx = lane + i * 32;
        float4 gg = gp[idx], bb = bp[idx];
        __half2 h0 = __floats2half2_rn((v[i].x - mean) * rs * gg.x + bb.x,
                                       (v[i].y - mean) * rs * gg.y + bb.y);
        __half2 h1 = __floats2half2_rn((v[i].z - mean) * rs * gg.z + bb.z,
                                       (v[i].w - mean) * rs * gg.w + bb.w);
        __half2 t[2] = { h0, h1 };
        *reinterpret_cast<uint2*>(out + row * DD + idx * 4) = *reinterpret_cast<uint2*>(t);
    }
}

// ---------------------------------------------------------------------------
// MMA-based fused shifted-window attention (fused qkv input, stride 1536)
// ---------------------------------------------------------------------------
#define ATS 40

__device__ __forceinline__ int region9(int h, int wv) {
    return ((h < 56) ? 0 : (h < 60) ? 1 : 2) * 3 + ((wv < 56) ? 0 : (wv < 60) ? 1 : 2);
}

__global__ void __launch_bounds__(128) attn_mma(
    const __half* __restrict__ qkv,
    const __half* __restrict__ bias64, __half* __restrict__ out)
{
    __shared__ __half qs[64 * ATS];
    __shared__ __half ks[64 * ATS];
    __shared__ __half vs[64 * ATS];

    const int tid = threadIdx.x;
    const int lane = tid & 31, w = tid >> 5;
    const int g = lane >> 2, tg = lane & 3;
    const int win = blockIdx.x, head = blockIdx.y, b = blockIdx.z;
    const int wi = win >> 3, wj = win & 7;
    const bool edge = (wi == 7) || (wj == 7);

    uint32_t sq = smem_to_u32(qs), sk = smem_to_u32(ks), sv = smem_to_u32(vs);

#pragma unroll
    for (int i = 0; i < 2; i++) {
        int ch = i * 128 + tid;
        int t = ch >> 2, part = (ch & 3) * 8;
        int hr = wi * 8 + (t >> 3), wr = wj * 8 + (t & 7);
        int hs = (hr + SHH) & (HH - 1), ws2 = (wr + SHH) & (WWD - 1);
        const __half* p = qkv + ((size_t)(b * HH + hs) * WWD + ws2) * 1536 + head * DKK + part;
        cp_async16(sq + (t * ATS + part) * 2, p);
        cp_async16(sk + (t * ATS + part) * 2, p + DD);
        cp_async16(sv + (t * ATS + part) * 2, p + 2 * DD);
    }
    CP_COMMIT();
    cp_wait_group<0>();
    __syncthreads();

    const int q0 = w * 16;
    const int lrow = lane & 15, lcol8 = (lane >> 4) * 8;

    float sc[8][4];
#pragma unroll
    for (int j = 0; j < 8; j++)
#pragma unroll
        for (int k2 = 0; k2 < 4; k2++) sc[j][k2] = 0.f;

    uint32_t aq[2][4];
    ldsm_x4(aq[0], sq + ((q0 + lrow) * ATS + 0  + lcol8) * 2);
    ldsm_x4(aq[1], sq + ((q0 + lrow) * ATS + 16 + lcol8) * 2);

    const int keyb = (lane & 7) + ((lane >> 4) << 3);
    const int kcb  = ((lane >> 3) & 1) << 3;
#pragma unroll
    for (int kk2 = 0; kk2 < 2; kk2++) {
#pragma unroll
        for (int np = 0; np < 4; np++) {
            uint32_t r4[4];
            ldsm_x4(r4, sk + ((np * 16 + keyb) * ATS + kk2 * 16 + kcb) * 2);
            uint32_t b0[2] = { r4[0], r4[1] }, b1[2] = { r4[2], r4[3] };
            mma_f16(sc[2 * np],     aq[kk2], b0);
            mma_f16(sc[2 * np + 1], aq[kk2], b1);
        }
    }

    const float SCALE = 0.17677669529663687f;
    const int tlo = q0 + g, thi = tlo + 8;
    const __half2* gb2 = reinterpret_cast<const __half2*>(bias64 + head * 4096);

    int idqlo = 0, idqhi = 0;
    if (edge) {
        idqlo = region9(wi * 8 + (tlo >> 3), wj * 8 + (tlo & 7));
        idqhi = region9(wi * 8 + (thi >> 3), wj * 8 + (thi & 7));
    }

    float f[8][4];
    float mlo = -1e30f, mhi = -1e30f;
#pragma unroll
    for (int j = 0; j < 8; j++) {
        __half2 blo = gb2[tlo * 32 + j * 4 + tg];
        __half2 bhi = gb2[thi * 32 + j * 4 + tg];
        float2 flo = __half22float2(blo), fhi = __half22float2(bhi);
        f[j][0] = sc[j][0] * SCALE + flo.x;
        f[j][1] = sc[j][1] * SCALE + flo.y;
        f[j][2] = sc[j][2] * SCALE + fhi.x;
        f[j][3] = sc[j][3] * SCALE + fhi.y;
        if (edge) {
            int c0 = j * 8 + tg * 2;
            int rk = c0 >> 3, ck0 = c0 & 7;
            int idr = ((wi * 8 + rk) < 56 ? 0 : (wi * 8 + rk) < 60 ? 1 : 2) * 3;
            int wk0 = wj * 8 + ck0, wk1 = wk0 + 1;
            int idk0 = idr + (wk0 < 56 ? 0 : wk0 < 60 ? 1 : 2);
            int idk1 = idr + (wk1 < 56 ? 0 : wk1 < 60 ? 1 : 2);
            if (idk0 != idqlo) f[j][0] = -1e9f;
            if (idk1 != idqlo) f[j][1] = -1e9f;
            if (idk0 != idqhi) f[j][2] = -1e9f;
            if (idk1 != idqhi) f[j][3] = -1e9f;
        }
        mlo = fmaxf(mlo, fmaxf(f[j][0], f[j][1]));
        mhi = fmaxf(mhi, fmaxf(f[j][2], f[j][3]));
    }
    mlo = fmaxf(mlo, __shfl_xor_sync(0xFFFFFFFFu, mlo, 1));
    mlo = fmaxf(mlo, __shfl_xor_sync(0xFFFFFFFFu, mlo, 2));
    mhi = fmaxf(mhi, __shfl_xor_sync(0xFFFFFFFFu, mhi, 1));
    mhi = fmaxf(mhi, __shfl_xor_sync(0xFFFFFFFFu, mhi, 2));

    float dlo = 0.f, dhi = 0.f;
    uint32_t ph[8][2];
#pragma unroll
    for (int j = 0; j < 8; j++) {
        float p0 = __expf(f[j][0] - mlo), p1 = __expf(f[j][1] - mlo);
        float p2 = __expf(f[j][2] - mhi), p3 = __expf(f[j][3] - mhi);
        dlo += p0 + p1; dhi += p2 + p3;
        __half2 hlo = __floats2half2_rn(p0, p1);
        __half2 hhi = __floats2half2_rn(p2, p3);
        ph[j][0] = *reinterpret_cast<uint32_t*>(&hlo);
        ph[j][1] = *reinterpret_cast<uint32_t*>(&hhi);
    }
    dlo += __shfl_xor_sync(0xFFFFFFFFu, dlo, 1);
    dlo += __shfl_xor_sync(0xFFFFFFFFu, dlo, 2);
    dhi += __shfl_xor_sync(0xFFFFFFFFu, dhi, 1);
    dhi += __shfl_xor_sync(0xFFFFFFFFu, dhi, 2);
    float invl = 1.f / dlo, invh = 1.f / dhi;

    float av[4][4];
#pragma unroll
    for (int j = 0; j < 4; j++)
#pragma unroll
        for (int k2 = 0; k2 < 4; k2++) av[j][k2] = 0.f;

#pragma unroll
    for (int j2 = 0; j2 < 4; j2++) {
        uint32_t a[4] = { ph[2*j2][0], ph[2*j2][1], ph[2*j2+1][0], ph[2*j2+1][1] };
#pragma unroll
        for (int np = 0; np < 2; np++) {
            uint32_t r4[4];
            ldsm_x4_t(r4, sv + ((j2 * 16 + lrow) * ATS + np * 16 + lcol8) * 2);
            uint32_t b0[2] = { r4[0], r4[1] }, b1[2] = { r4[2], r4[3] };
            mma_f16(av[2 * np],     a, b0);
            mma_f16(av[2 * np + 1], a, b1);
        }
    }

    {
        int hr = wi * 8 + (tlo >> 3), wr = wj * 8 + (tlo & 7);
        size_t blo = ((size_t)(b * HH + ((hr + SHH) & (HH - 1))) * WWD + ((wr + SHH) & (WWD - 1)));
        hr = wi * 8 + (thi >> 3); wr = wj * 8 + (thi & 7);
        size_t bhi = ((size_t)(b * HH + ((hr + SHH) & (HH - 1))) * WWD + ((wr + SHH) & (WWD - 1)));
        __half* olo = out + blo * DD + head * DKK;
        __half* ohi = out + bhi * DD + head * DKK;
#pragma unroll
        for (int nt = 0; nt < 4; nt++) {
            *reinterpret_cast<__half2*>(olo + nt * 8 + tg * 2) =
                __floats2half2_rn(av[nt][0] * invl, av[nt][1] * invl);
            *reinterpret_cast<__half2*>(ohi + nt * 8 + tg * 2) =
                __floats2half2_rn(av[nt][2] * invh, av[nt][3] * invh);
        }
    }
}

// ---------------------------------------------------------------------------
extern "C" void kernel_launch(void* const* d_in, const int* in_sizes, int n_in,
                              void* d_out, int out_size) {
    const float* x   = (const float*)d_in[0];
    const float* Wq  = (const float*)d_in[3];
    const float* bq  = (const float*)d_in[4];
    const float* Wkv = (const float*)d_in[5];
    const float* bkv = (const float*)d_in[6];
    const float* Wo  = (const float*)d_in[7];
    const float* bo  = (const float*)d_in[8];
    const float* rt  = (const float*)d_in[9];
    const float* l1g = (const float*)d_in[10];
    const float* l1b = (const float*)d_in[11];
    const float* l2g = (const float*)d_in[12];
    const float* l2b = (const float*)d_in[13];
    const float* W1  = (const float*)d_in[14];
    const float* b1  = (const float*)d_in[15];
    const float* W2  = (const float*)d_in[16];
    const float* b2  = (const float*)d_in[17];
    float* xo = (float*)d_out;

    __half *pqkv, *pxn, *pat, *ph, *wqkv16, *wo16, *w1_16, *w2_16, *pbias;
    float* bqkv;
    cudaGetSymbolAddress((void**)&pqkv,   g_qkv16);
    cudaGetSymbolAddress((void**)&pxn,    g_xn16);
    cudaGetSymbolAddress((void**)&pat,    g_at16);
    cudaGetSymbolAddress((void**)&ph,     g_h16);
    cudaGetSymbolAddress((void**)&wqkv16, g_wqkv16);
    cudaGetSymbolAddress((void**)&bqkv,   g_bqkv);
    cudaGetSymbolAddress((void**)&wo16,   g_wo16);
    cudaGetSymbolAddress((void**)&w1_16,  g_w1_16);
    cudaGetSymbolAddress((void**)&w2_16,  g_w2_16);
    cudaGetSymbolAddress((void**)&pbias,  g_bias64);

    cudaFuncSetAttribute(hgemm<0, __half>, cudaFuncAttributeMaxDynamicSharedMemorySize, SMEM_H);
    cudaFuncSetAttribute(hgemm<1, __half>, cudaFuncAttributeMaxDynamicSharedMemorySize, SMEM_H);
    cudaFuncSetAttribute(hgemm<2, float>,  cudaFuncAttributeMaxDynamicSharedMemorySize, SMEM_H);

    prep_kernel<<<(U_TOTAL + 255) / 256, 256>>>(
        Wq, Wkv, Wo, W1, W2, rt, bq, bkv,
        wqkv16, wo16, w1_16, w2_16, pbias, bqkv);

    for (int l = 0; l < LL; l++) {
        const float* xin = (l == 0) ? x : xo;
        ln_kernel<<<MM / 8, 256>>>(xin, l1g + l * DD, l1b + l * DD, pxn);
        hgemm<0, __half><<<dim3(12, MM / 128), 128, SMEM_H>>>(
            pxn, wqkv16 + (size_t)l * DD * 3 * DD, bqkv + (size_t)l * 3 * DD,
            nullptr, pqkv, MM, 3 * DD, DD);
        attn_mma<<<dim3(64, NHH, BB), 128>>>(pqkv, pbias + (size_t)l * NHH * 4096, pat);
        hgemm<2, float><<<dim3(DD / 128, MM / 128), 128, SMEM_H>>>(
            pat, wo16 + (size_t)l * DD * DD, bo + (size_t)l * DD, xin, xo,
            MM, DD, DD);
        ln_kernel<<<MM / 8, 256>>>(xo, l2g + l * DD, l2b + l * DD, pxn);
        hgemm<1, __half><<<dim3(4 * DD / 128, MM / 128), 128, SMEM_H>>>(
            pxn, w1_16 + (size_t)l * DD * 4 * DD, b1 + (size_t)l * 4 * DD, nullptr, ph,
            MM, 4 * DD, DD);
        hgemm<2, float><<<dim3(DD / 128, MM / 128), 128, SMEM_H>>>(
            ph, w2_16 + (size_t)l * 4 * DD * DD, b2 + (size_t)l * DD, xo, xo,
            MM, DD, 4 * DD);
    }
}

// round 17
// speedup vs baseline: 1.5055x; 1.5055x over previous
#include <cuda_runtime.h>
#include <cuda_fp16.h>
#include <cstdint>

// Problem constants
#define BB   8
#define HH   64
#define WWD  64
#define DD   512
#define NHH  16
#define DKK  32
#define WSS  8
#define SHH  4
#define LL   4
#define MM   (BB*HH*WWD)          // 32768 tokens

// Scratch (device globals)
__device__ __half g_q16 [(size_t)MM * DD];
__device__ __half g_kv16[(size_t)MM * 2 * DD];
__device__ __half g_xn16[(size_t)MM * DD];
__device__ __half g_at16[(size_t)MM * DD];
__device__ __half g_h16 [(size_t)MM * 4 * DD];
__device__ __half g_wq16 [(size_t)LL * DD * DD];
__device__ __half g_wkv16[(size_t)LL * DD * 2 * DD];
__device__ __half g_wo16 [(size_t)LL * DD * DD];
__device__ __half g_w1_16[(size_t)LL * DD * 4 * DD];
__device__ __half g_w2_16[(size_t)LL * 4 * DD * DD];
__device__ __half g_bias64[(size_t)LL * NHH * 64 * 64];

// ---------------------------------------------------------------------------
// Baseline-PTX helpers
// ---------------------------------------------------------------------------
__device__ __forceinline__ uint32_t smem_to_u32(const void* p) {
    uint32_t a;
    asm("{ .reg .u64 t; cvta.to.shared.u64 t, %1; cvt.u32.u64 %0, t; }" : "=r"(a) : "l"(p));
    return a;
}
__device__ __forceinline__ void cp_async16(uint32_t dst, const void* src) {
    asm volatile("cp.async.cg.shared.global [%0], [%1], 16;" :: "r"(dst), "l"(src));
}
#define CP_COMMIT() asm volatile("cp.async.commit_group;" ::: "memory")
template <int N> __device__ __forceinline__ void cp_wait_group() {
    asm volatile("cp.async.wait_group %0;" :: "n"(N) : "memory");
}
__device__ __forceinline__ void ldsm_x4(uint32_t* r, uint32_t addr) {
    asm volatile("ldmatrix.sync.aligned.m8n8.x4.shared.b16 {%0,%1,%2,%3}, [%4];"
        : "=r"(r[0]), "=r"(r[1]), "=r"(r[2]), "=r"(r[3]) : "r"(addr));
}
__device__ __forceinline__ void ldsm_x4_t(uint32_t* r, uint32_t addr) {
    asm volatile("ldmatrix.sync.aligned.m8n8.x4.trans.shared.b16 {%0,%1,%2,%3}, [%4];"
        : "=r"(r[0]), "=r"(r[1]), "=r"(r[2]), "=r"(r[3]) : "r"(addr));
}
__device__ __forceinline__ void mma_f16(float* c, const uint32_t* a, const uint32_t* b) {
    asm volatile(
        "mma.sync.aligned.m16n8k16.row.col.f32.f16.f16.f32 "
        "{%0,%1,%2,%3}, {%4,%5,%6,%7}, {%8,%9}, {%0,%1,%2,%3};\n"
        : "+f"(c[0]), "+f"(c[1]), "+f"(c[2]), "+f"(c[3])
        : "r"(a[0]), "r"(a[1]), "r"(a[2]), "r"(a[3]), "r"(b[0]), "r"(b[1]));
}

// ---------------------------------------------------------------------------
// fp16 tensor-core GEMM (R10/R14 best config: 2-stage smem dbuf + reg frag dbuf,
// 128 threads, 4 warps with 64x64 warp tiles, 2 CTAs/SM)
// ---------------------------------------------------------------------------
#define HAS_STRIDE 72
#define HBS_STRIDE 136
#define HAS_BUF (128 * HAS_STRIDE)
#define HBS_BUF (64 * HBS_STRIDE)
#define SMEM_H  ((2 * HAS_BUF + 2 * HBS_BUF) * 2)   // 71680 bytes

__device__ __forceinline__ float gelu_f(float x) {
    float x3 = x * x * x;
    return 0.5f * x * (1.f + tanhf(0.7978845608028654f * (x + 0.044715f * x3)));
}
__device__ __forceinline__ void store2(float* C, size_t off, float v0, float v1) {
    float2 o; o.x = v0; o.y = v1;
    *reinterpret_cast<float2*>(C + off) = o;
}
__device__ __forceinline__ void store2(__half* C, size_t off, float v0, float v1) {
    *reinterpret_cast<__half2*>(C + off) = __floats2half2_rn(v0, v1);
}

__device__ __forceinline__ void load_frags(
    uint32_t sbA, uint32_t sbB, int kk, int wm, int wn, int lrow, int lcol8,
    uint32_t af[4][4], uint32_t bf[8][2])
{
#pragma unroll
    for (int mt = 0; mt < 4; mt++) {
        int m = wm * 64 + mt * 16 + lrow;
        ldsm_x4(af[mt], sbA + (m * HAS_STRIDE + kk + lcol8) * 2);
    }
#pragma unroll
    for (int np = 0; np < 4; np++) {
        uint32_t r4[4];
        int n = wn * 64 + np * 16 + lcol8;
        ldsm_x4_t(r4, sbB + ((kk + lrow) * HBS_STRIDE + n) * 2);
        bf[2*np][0]   = r4[0]; bf[2*np][1]   = r4[1];
        bf[2*np+1][0] = r4[2]; bf[2*np+1][1] = r4[3];
    }
}

template <int EPI, typename OutT>
__global__ void __launch_bounds__(128, 2) hgemm(
    const __half* __restrict__ A, const __half* __restrict__ Bm,
    const float* __restrict__ bias, const float* __restrict__ Rv,
    OutT* __restrict__ C, int M, int N, int K)
{
    extern __shared__ __half smh[];
    uint32_t sb = smem_to_u32(smh);
    const int tid = threadIdx.x;
    const int lane = tid & 31, wid = tid >> 5;
    const int wm = wid & 1, wn = wid >> 1;
    const int g = lane >> 2, tg = lane & 3;
    const int row0 = blockIdx.y * 128, col0 = blockIdx.x * 128;
    const int lrow = lane & 15, lcol8 = (lane >> 4) * 8;

    float acc[4][8][4];
#pragma unroll
    for (int i = 0; i < 4; i++)
#pragma unroll
        for (int j = 0; j < 8; j++)
#pragma unroll
            for (int k = 0; k < 4; k++) acc[i][j][k] = 0.f;

    const int NC = K >> 6;

    {
        uint32_t ad = sb, bd = sb + 2 * HAS_BUF * 2;
#pragma unroll
        for (int i = 0; i < 8; i++) {
            int ch = i * 128 + tid;
            int r = ch >> 3, c8 = ch & 7;
            cp_async16(ad + (r * HAS_STRIDE + c8 * 8) * 2,
                       A + (size_t)(row0 + r) * K + c8 * 8);
        }
#pragma unroll
        for (int i = 0; i < 8; i++) {
            int ch = i * 128 + tid;
            int r = ch >> 4, c8 = ch & 15;
            cp_async16(bd + (r * HBS_STRIDE + c8 * 8) * 2,
                       Bm + (size_t)r * N + col0 + c8 * 8);
        }
        CP_COMMIT();
    }

    uint32_t af[2][4][4], bf[2][8][2];

    for (int c = 0; c < NC; c++) {
        if (c + 1 < NC) {
            int kt = (c + 1) << 6;
            int nb = (c + 1) & 1;
            uint32_t ad = sb + (nb ? HAS_BUF * 2 : 0);
            uint32_t bd = sb + (2 * HAS_BUF + (nb ? HBS_BUF : 0)) * 2;
#pragma unroll
            for (int i = 0; i < 8; i++) {
                int ch = i * 128 + tid;
                int r = ch >> 3, c8 = ch & 7;
                cp_async16(ad + (r * HAS_STRIDE + c8 * 8) * 2,
                           A + (size_t)(row0 + r) * K + kt + c8 * 8);
            }
#pragma unroll
            for (int i = 0; i < 8; i++) {
                int ch = i * 128 + tid;
                int r = ch >> 4, c8 = ch & 15;
                cp_async16(bd + (r * HBS_STRIDE + c8 * 8) * 2,
                           Bm + (size_t)(kt + r) * N + col0 + c8 * 8);
            }
            CP_COMMIT();
            cp_wait_group<1>();
        } else {
            cp_wait_group<0>();
        }
        __syncthreads();

        uint32_t sbA = sb + ((c & 1) ? HAS_BUF * 2 : 0);
        uint32_t sbB = sb + (2 * HAS_BUF + ((c & 1) ? HBS_BUF : 0)) * 2;

        load_frags(sbA, sbB, 0, wm, wn, lrow, lcol8, af[0], bf[0]);
#pragma unroll
        for (int j = 0; j < 4; j++) {
            if (j < 3)
                load_frags(sbA, sbB, (j + 1) * 16, wm, wn, lrow, lcol8,
                           af[(j + 1) & 1], bf[(j + 1) & 1]);
            const int cur = j & 1;
#pragma unroll
            for (int mt = 0; mt < 4; mt++)
#pragma unroll
                for (int nt = 0; nt < 8; nt++)
                    mma_f16(acc[mt][nt], af[cur][mt], bf[cur][nt]);
        }
        __syncthreads();
    }

#pragma unroll
    for (int mt = 0; mt < 4; mt++) {
#pragma unroll
        for (int nt = 0; nt < 8; nt++) {
            int r = row0 + wm * 64 + mt * 16 + g;
            int cc = col0 + wn * 64 + nt * 8 + tg * 2;
            float b0 = bias[cc], b1 = bias[cc + 1];
#pragma unroll
            for (int h = 0; h < 2; h++) {
                int rr = r + h * 8;
                size_t off = (size_t)rr * N + cc;
                float v0 = acc[mt][nt][h * 2 + 0] + b0;
                float v1 = acc[mt][nt][h * 2 + 1] + b1;
                if (EPI == 1) { v0 = gelu_f(v0); v1 = gelu_f(v1); }
                if (EPI == 2) {
                    float2 rv = *reinterpret_cast<const float2*>(Rv + off);
                    v0 += rv.x; v1 += rv.y;
                }
                store2(C, off, v0, v1);
            }
        }
    }
}

// ---------------------------------------------------------------------------
// ONE prep kernel: convert Wq/Wkv/Wo/W1/W2 to fp16 + build bias64.
// ---------------------------------------------------------------------------
struct H8 { __half2 h[4]; };
#define U_WQ   (LL * DD * DD / 8)              // 131072
#define U_WKV  (LL * DD * 2 * DD / 8)          // 262144
#define U_WO   (LL * DD * DD / 8)              // 131072
#define U_W1   (LL * DD * 4 * DD / 8)          // 524288
#define U_W2   (LL * 4 * DD * DD / 8)          // 524288
#define U_BIAS (LL * NHH * 64 * 64 / 8)        // 32768
#define U_TOTAL (U_WQ + U_WKV + U_WO + U_W1 + U_W2 + U_BIAS)

__device__ __forceinline__ void cvt8(const float* src, __half* dst) {
    const float4* p = reinterpret_cast<const float4*>(src);
    float4 a = p[0], b = p[1];
    H8 o;
    o.h[0] = __floats2half2_rn(a.x, a.y);
    o.h[1] = __floats2half2_rn(a.z, a.w);
    o.h[2] = __floats2half2_rn(b.x, b.y);
    o.h[3] = __floats2half2_rn(b.z, b.w);
    *reinterpret_cast<H8*>(dst) = o;
}

__global__ void prep_kernel(
    const float* __restrict__ Wq, const float* __restrict__ Wkv,
    const float* __restrict__ Wo, const float* __restrict__ W1,
    const float* __restrict__ W2, const float* __restrict__ rt,
    __half* __restrict__ wq, __half* __restrict__ wkv,
    __half* __restrict__ wo, __half* __restrict__ w1,
    __half* __restrict__ w2, __half* __restrict__ bias64)
{
    int u = blockIdx.x * blockDim.x + threadIdx.x;
    if (u < U_WQ)  { cvt8(Wq  + (size_t)u * 8, wq  + (size_t)u * 8); return; }
    u -= U_WQ;
    if (u < U_WKV) { cvt8(Wkv + (size_t)u * 8, wkv + (size_t)u * 8); return; }
    u -= U_WKV;
    if (u < U_WO)  { cvt8(Wo  + (size_t)u * 8, wo  + (size_t)u * 8); return; }
    u -= U_WO;
    if (u < U_W1)  { cvt8(W1  + (size_t)u * 8, w1  + (size_t)u * 8); return; }
    u -= U_W1;
    if (u < U_W2)  { cvt8(W2  + (size_t)u * 8, w2  + (size_t)u * 8); return; }
    u -= U_W2;
    if (u < U_BIAS) {
        size_t base = (size_t)u * 8;
        int kk0 = (int)(base & 63);
        int qq  = (int)((base >> 6) & 63);
        int h   = (int)((base >> 12) & (NHH - 1));
        int l   = (int)(base >> 16);
        int rq = qq >> 3, cq = qq & 7;
        __half v[8];
#pragma unroll
        for (int e = 0; e < 8; e++) {
            int kk = kk0 + e;
            int rk = kk >> 3, ck = kk & 7;
            int ti = (rq - rk + 7) * 15 + (cq - ck + 7);
            v[e] = __float2half_rn(rt[((size_t)l * 225 + ti) * NHH + h]);
        }
        *reinterpret_cast<H8*>(bias64 + base) = *reinterpret_cast<H8*>(v);
    }
}

// ---------------------------------------------------------------------------
// LayerNorm: one warp per token, fp16 output
// ---------------------------------------------------------------------------
__global__ void ln_kernel(const float* __restrict__ x, const float* __restrict__ g,
                          const float* __restrict__ b, __half* __restrict__ out) {
    int warp = threadIdx.x >> 5, lane = threadIdx.x & 31;
    size_t row = (size_t)blockIdx.x * 8 + warp;
    const float4* xp = reinterpret_cast<const float4*>(x + row * DD);
    float4 v[4];
    float s = 0.f;
#pragma unroll
    for (int i = 0; i < 4; i++) {
        v[i] = xp[lane + i * 32];
        s += v[i].x + v[i].y + v[i].z + v[i].w;
    }
#pragma unroll
    for (int o = 16; o; o >>= 1) s += __shfl_xor_sync(0xFFFFFFFFu, s, o);
    float mean = s * (1.f / DD);
    float vs = 0.f;
#pragma unroll
    for (int i = 0; i < 4; i++) {
        float dx;
        dx = v[i].x - mean; vs += dx * dx;
        dx = v[i].y - mean; vs += dx * dx;
        dx = v[i].z - mean; vs += dx * dx;
        dx = v[i].w - mean; vs += dx * dx;
    }
#pragma unroll
    for (int o = 16; o; o >>= 1) vs += __shfl_xor_sync(0xFFFFFFFFu, vs, o);
    float rs = rsqrtf(vs * (1.f / DD) + 1e-5f);
    const float4* gp = reinterpret_cast<const float4*>(g);
    const float4* bp = reinterpret_cast<const float4*>(b);
#pragma unroll
    for (int i = 0; i < 4; i++) {
        int idx = lane + i * 32;
        float4 gg = gp[idx], bb = bp[idx];
        __half2 h0 = __floats2half2_rn((v[i].x - mean) * rs * gg.x + bb.x,
                                       (v[i].y - mean) * rs * gg.y + bb.y);
        __half2 h1 = __floats2half2_rn((v[i].z - mean) * rs * gg.z + bb.z,
                                       (v[i].w - mean) * rs * gg.w + bb.w);
        __half2 t[2] = { h0, h1 };
        *reinterpret_cast<uint2*>(out + row * DD + idx * 4) = *reinterpret_cast<uint2*>(t);
    }
}

// ---------------------------------------------------------------------------
// MMA-based fused shifted-window attention (R14 version: split q/kv inputs,
// precomputed bias64, analytic edge mask)
// ---------------------------------------------------------------------------
#define ATS 40

__device__ __forceinline__ int region9(int h, int wv) {
    return ((h < 56) ? 0 : (h < 60) ? 1 : 2) * 3 + ((wv < 56) ? 0 : (wv < 60) ? 1 : 2);
}

__global__ void __launch_bounds__(128) attn_mma(
    const __half* __restrict__ q, const __half* __restrict__ kv,
    const __half* __restrict__ bias64, __half* __restrict__ out)
{
    __shared__ __half qs[64 * ATS];
    __shared__ __half ks[64 * ATS];
    __shared__ __half vs[64 * ATS];

    const int tid = threadIdx.x;
    const int lane = tid & 31, w = tid >> 5;
    const int g = lane >> 2, tg = lane & 3;
    const int win = blockIdx.x, head = blockIdx.y, b = blockIdx.z;
    const int wi = win >> 3, wj = win & 7;
    const bool edge = (wi == 7) || (wj == 7);

    uint32_t sq = smem_to_u32(qs), sk = smem_to_u32(ks), sv = smem_to_u32(vs);

#pragma unroll
    for (int i = 0; i < 2; i++) {
        int ch = i * 128 + tid;
        int t = ch >> 2, part = (ch & 3) * 8;
        int hr = wi * 8 + (t >> 3), wr = wj * 8 + (t & 7);
        int hs = (hr + SHH) & (HH - 1), ws2 = (wr + SHH) & (WWD - 1);
        size_t base = ((size_t)(b * HH + hs) * WWD + ws2);
        cp_async16(sq + (t * ATS + part) * 2, q  + base * DD     + head * DKK + part);
        cp_async16(sk + (t * ATS + part) * 2, kv + base * 2 * DD + head * DKK + part);
        cp_async16(sv + (t * ATS + part) * 2, kv + base * 2 * DD + DD + head * DKK + part);
    }
    CP_COMMIT();
    cp_wait_group<0>();
    __syncthreads();

    const int q0 = w * 16;
    const int lrow = lane & 15, lcol8 = (lane >> 4) * 8;

    float sc[8][4];
#pragma unroll
    for (int j = 0; j < 8; j++)
#pragma unroll
        for (int k2 = 0; k2 < 4; k2++) sc[j][k2] = 0.f;

    uint32_t aq[2][4];
    ldsm_x4(aq[0], sq + ((q0 + lrow) * ATS + 0  + lcol8) * 2);
    ldsm_x4(aq[1], sq + ((q0 + lrow) * ATS + 16 + lcol8) * 2);

    const int keyb = (lane & 7) + ((lane >> 4) << 3);
    const int kcb  = ((lane >> 3) & 1) << 3;
#pragma unroll
    for (int kk2 = 0; kk2 < 2; kk2++) {
#pragma unroll
        for (int np = 0; np < 4; np++) {
            uint32_t r4[4];
            ldsm_x4(r4, sk + ((np * 16 + keyb) * ATS + kk2 * 16 + kcb) * 2);
            uint32_t b0[2] = { r4[0], r4[1] }, b1[2] = { r4[2], r4[3] };
            mma_f16(sc[2 * np],     aq[kk2], b0);
            mma_f16(sc[2 * np + 1], aq[kk2], b1);
        }
    }

    const float SCALE = 0.17677669529663687f;
    const int tlo = q0 + g, thi = tlo + 8;
    const __half2* gb2 = reinterpret_cast<const __half2*>(bias64 + head * 4096);

    int idqlo = 0, idqhi = 0;
    if (edge) {
        idqlo = region9(wi * 8 + (tlo >> 3), wj * 8 + (tlo & 7));
        idqhi = region9(wi * 8 + (thi >> 3), wj * 8 + (thi & 7));
    }

    float f[8][4];
    float mlo = -1e30f, mhi = -1e30f;
#pragma unroll
    for (int j = 0; j < 8; j++) {
        __half2 blo = gb2[tlo * 32 + j * 4 + tg];
        __half2 bhi = gb2[thi * 32 + j * 4 + tg];
        float2 flo = __half22float2(blo), fhi = __half22float2(bhi);
        f[j][0] = sc[j][0] * SCALE + flo.x;
        f[j][1] = sc[j][1] * SCALE + flo.y;
        f[j][2] = sc[j][2] * SCALE + fhi.x;
        f[j][3] = sc[j][3] * SCALE + fhi.y;
        if (edge) {
            int c0 = j * 8 + tg * 2;
            int rk = c0 >> 3, ck0 = c0 & 7;
            int idr = ((wi * 8 + rk) < 56 ? 0 : (wi * 8 + rk) < 60 ? 1 : 2) * 3;
            int wk0 = wj * 8 + ck0, wk1 = wk0 + 1;
            int idk0 = idr + (wk0 < 56 ? 0 : wk0 < 60 ? 1 : 2);
            int idk1 = idr + (wk1 < 56 ? 0 : wk1 < 60 ? 1 : 2);
            if (idk0 != idqlo) f[j][0] = -1e9f;
            if (idk1 != idqlo) f[j][1] = -1e9f;
            if (idk0 != idqhi) f[j][2] = -1e9f;
            if (idk1 != idqhi) f[j][3] = -1e9f;
        }
        mlo = fmaxf(mlo, fmaxf(f[j][0], f[j][1]));
        mhi = fmaxf(mhi, fmaxf(f[j][2], f[j][3]));
    }
    mlo = fmaxf(mlo, __shfl_xor_sync(0xFFFFFFFFu, mlo, 1));
    mlo = fmaxf(mlo, __shfl_xor_sync(0xFFFFFFFFu, mlo, 2));
    mhi = fmaxf(mhi, __shfl_xor_sync(0xFFFFFFFFu, mhi, 1));
    mhi = fmaxf(mhi, __shfl_xor_sync(0xFFFFFFFFu, mhi, 2));

    float dlo = 0.f, dhi = 0.f;
    uint32_t ph[8][2];
#pragma unroll
    for (int j = 0; j < 8; j++) {
        float p0 = __expf(f[j][0] - mlo), p1 = __expf(f[j][1] - mlo);
        float p2 = __expf(f[j][2] - mhi), p3 = __expf(f[j][3] - mhi);
        dlo += p0 + p1; dhi += p2 + p3;
        __half2 hlo = __floats2half2_rn(p0, p1);
        __half2 hhi = __floats2half2_rn(p2, p3);
        ph[j][0] = *reinterpret_cast<uint32_t*>(&hlo);
        ph[j][1] = *reinterpret_cast<uint32_t*>(&hhi);
    }
    dlo += __shfl_xor_sync(0xFFFFFFFFu, dlo, 1);
    dlo += __shfl_xor_sync(0xFFFFFFFFu, dlo, 2);
    dhi += __shfl_xor_sync(0xFFFFFFFFu, dhi, 1);
    dhi += __shfl_xor_sync(0xFFFFFFFFu, dhi, 2);
    float invl = 1.f / dlo, invh = 1.f / dhi;

    float av[4][4];
#pragma unroll
    for (int j = 0; j < 4; j++)
#pragma unroll
        for (int k2 = 0; k2 < 4; k2++) av[j][k2] = 0.f;

#pragma unroll
    for (int j2 = 0; j2 < 4; j2++) {
        uint32_t a[4] = { ph[2*j2][0], ph[2*j2][1], ph[2*j2+1][0], ph[2*j2+1][1] };
#pragma unroll
        for (int np = 0; np < 2; np++) {
            uint32_t r4[4];
            ldsm_x4_t(r4, sv + ((j2 * 16 + lrow) * ATS + np * 16 + lcol8) * 2);
            uint32_t b0[2] = { r4[0], r4[1] }, b1[2] = { r4[2], r4[3] };
            mma_f16(av[2 * np],     a, b0);
            mma_f16(av[2 * np + 1], a, b1);
        }
    }

    {
        int hr = wi * 8 + (tlo >> 3), wr = wj * 8 + (tlo & 7);
        size_t blo = ((size_t)(b * HH + ((hr + SHH) & (HH - 1))) * WWD + ((wr + SHH) & (WWD - 1)));
        hr = wi * 8 + (thi >> 3); wr = wj * 8 + (thi & 7);
        size_t bhi = ((size_t)(b * HH + ((hr + SHH) & (HH - 1))) * WWD + ((wr + SHH) & (WWD - 1)));
        __half* olo = out + blo * DD + head * DKK;
        __half* ohi = out + bhi * DD + head * DKK;
#pragma unroll
        for (int nt = 0; nt < 4; nt++) {
            *reinterpret_cast<__half2*>(olo + nt * 8 + tg * 2) =
                __floats2half2_rn(av[nt][0] * invl, av[nt][1] * invl);
            *reinterpret_cast<__half2*>(ohi + nt * 8 + tg * 2) =
                __floats2half2_rn(av[nt][2] * invh, av[nt][3] * invh);
        }
    }
}

// ---------------------------------------------------------------------------
extern "C" void kernel_launch(void* const* d_in, const int* in_sizes, int n_in,
                              void* d_out, int out_size) {
    const float* x   = (const float*)d_in[0];
    const float* Wq  = (const float*)d_in[3];
    const float* bq  = (const float*)d_in[4];
    const float* Wkv = (const float*)d_in[5];
    const float* bkv = (const float*)d_in[6];
    const float* Wo  = (const float*)d_in[7];
    const float* bo  = (const float*)d_in[8];
    const float* rt  = (const float*)d_in[9];
    const float* l1g = (const float*)d_in[10];
    const float* l1b = (const float*)d_in[11];
    const float* l2g = (const float*)d_in[12];
    const float* l2b = (const float*)d_in[13];
    const float* W1  = (const float*)d_in[14];
    const float* b1  = (const float*)d_in[15];
    const float* W2  = (const float*)d_in[16];
    const float* b2  = (const float*)d_in[17];
    float* xo = (float*)d_out;

    __half *pq, *pkv, *pxn, *pat, *ph, *wq16, *wkv16, *wo16, *w1_16, *w2_16, *pbias;
    cudaGetSymbolAddress((void**)&pq,    g_q16);
    cudaGetSymbolAddress((void**)&pkv,   g_kv16);
    cudaGetSymbolAddress((void**)&pxn,   g_xn16);
    cudaGetSymbolAddress((void**)&pat,   g_at16);
    cudaGetSymbolAddress((void**)&ph,    g_h16);
    cudaGetSymbolAddress((void**)&wq16,  g_wq16);
    cudaGetSymbolAddress((void**)&wkv16, g_wkv16);
    cudaGetSymbolAddress((void**)&wo16,  g_wo16);
    cudaGetSymbolAddress((void**)&w1_16, g_w1_16);
    cudaGetSymbolAddress((void**)&w2_16, g_w2_16);
    cudaGetSymbolAddress((void**)&pbias, g_bias64);

    cudaFuncSetAttribute(hgemm<0, __half>, cudaFuncAttributeMaxDynamicSharedMemorySize, SMEM_H);
    cudaFuncSetAttribute(hgemm<1, __half>, cudaFuncAttributeMaxDynamicSharedMemorySize, SMEM_H);
    cudaFuncSetAttribute(hgemm<2, float>,  cudaFuncAttributeMaxDynamicSharedMemorySize, SMEM_H);

    // single prep launch: convert weights + build bias
    prep_kernel<<<(U_TOTAL + 255) / 256, 256>>>(
        Wq, Wkv, Wo, W1, W2, rt, wq16, wkv16, wo16, w1_16, w2_16, pbias);

    for (int l = 0; l < LL; l++) {
        const float* xin = (l == 0) ? x : xo;   // no initial memcpy
        ln_kernel<<<MM / 8, 256>>>(xin, l1g + l * DD, l1b + l * DD, pxn);
        hgemm<0, __half><<<dim3(DD / 128, MM / 128), 128, SMEM_H>>>(
            pxn, wq16 + (size_t)l * DD * DD, bq + (size_t)l * DD, nullptr, pq,
            MM, DD, DD);
        hgemm<0, __half><<<dim3(2 * DD / 128, MM / 128), 128, SMEM_H>>>(
            pxn, wkv16 + (size_t)l * DD * 2 * DD, bkv + (size_t)l * 2 * DD, nullptr, pkv,
            MM, 2 * DD, DD);
        attn_mma<<<dim3(64, NHH, BB), 128>>>(pq, pkv, pbias + (size_t)l * NHH * 4096, pat);
        hgemm<2, float><<<dim3(DD / 128, MM / 128), 128, SMEM_H>>>(
            pat, wo16 + (size_t)l * DD * DD, bo + (size_t)l * DD, xin, xo,
            MM, DD, DD);
        ln_kernel<<<MM / 8, 256>>>(xo, l2g + l * DD, l2b + l * DD, pxn);
        hgemm<1, __half><<<dim3(4 * DD / 128, MM / 128), 128, SMEM_H>>>(
            pxn, w1_16 + (size_t)l * DD * 4 * DD, b1 + (size_t)l * 4 * DD, nullptr, ph,
            MM, 4 * DD, DD);
        hgemm<2, float><<<dim3(DD / 128, MM / 128), 128, SMEM_H>>>(
            ph, w2_16 + (size_t)l * 4 * DD * DD, b2 + (size_t)l * DD, xo, xo,
            MM, DD, 4 * DD);
    }
}